// round 4
// baseline (speedup 1.0000x reference)
#include <cuda_runtime.h>

// Problem constants (fixed by setup_inputs)
#define HH 256
#define WW 256
#define BB 4
#define CC 64
#define KOFF 18          // 2*K*K
#define HWP (HH*WW)      // 65536

// Scratch (device-global; no allocation allowed)
__device__ float g_feat[BB*CC*HH*WW];     // 64 MiB
__device__ float g_off [BB*KOFF*HH*WW];   // 18 MiB

// ---------------------------------------------------------------------------
// Packed f32x2 helpers (FFMA2 — only reachable via PTX fma.rn.f32x2)
// ---------------------------------------------------------------------------
typedef unsigned long long u64;

__device__ __forceinline__ void fma2(u64 &d, u64 a, u64 b) {
    asm("fma.rn.f32x2 %0, %1, %2, %0;" : "+l"(d) : "l"(a), "l"(b));
}
__device__ __forceinline__ u64 pack2(float lo, float hi) {
    u64 r; asm("mov.b64 %0, {%1, %2};" : "=l"(r) : "f"(lo), "f"(hi)); return r;
}
__device__ __forceinline__ void unpack2(u64 v, float &lo, float &hi) {
    asm("mov.b64 {%0, %1}, %2;" : "=f"(lo), "=f"(hi) : "l"(v));
}

// ---------------------------------------------------------------------------
// Kernel 1: conv1  x[4,3,256,256] -> g_feat[4,64,256,256], 3x3 pad 1
// (proven round-1 scalar version: 128 regs -> 2 CTAs/SM, 41.6us)
// ---------------------------------------------------------------------------
__global__ __launch_bounds__(256) void conv1_kernel(
    const float* __restrict__ x, const float* __restrict__ w,
    const float* __restrict__ bias)
{
    __shared__ __align__(16) float w_sh[27][64];   // [c*9+kk][oc]
    __shared__ float b_sh[64];
    int tid = threadIdx.x;
    for (int idx = tid; idx < 64*27; idx += 256) {
        int oc = idx / 27, r = idx % 27;           // w: [oc][c][ky][kx]
        w_sh[r][oc] = w[idx];
    }
    if (tid < 64) b_sh[tid] = bias[tid];
    __syncthreads();

    int px  = blockIdx.x * 256 + tid;
    int b   = px >> 16;
    int rem = px & 0xFFFF;
    int oy  = rem >> 8, ox = rem & 255;

    float in[27];
    #pragma unroll
    for (int c = 0; c < 3; c++)
        #pragma unroll
        for (int ky = 0; ky < 3; ky++)
            #pragma unroll
            for (int kx = 0; kx < 3; kx++) {
                int iy = oy + ky - 1, ix = ox + kx - 1;
                bool ok = (iy >= 0 && iy < HH && ix >= 0 && ix < WW);
                in[c*9 + ky*3 + kx] = ok ? __ldg(&x[((b*3 + c)*HH + iy)*WW + ix]) : 0.f;
            }

    float acc[64];
    #pragma unroll
    for (int oc = 0; oc < 64; oc++) acc[oc] = b_sh[oc];

    #pragma unroll
    for (int r = 0; r < 27; r++) {
        float v = in[r];
        #pragma unroll
        for (int oc = 0; oc < 64; oc += 4) {
            float4 wv = *(const float4*)&w_sh[r][oc];
            acc[oc+0] += v * wv.x;  acc[oc+1] += v * wv.y;
            acc[oc+2] += v * wv.z;  acc[oc+3] += v * wv.w;
        }
    }
    int pix = oy*WW + ox;
    #pragma unroll
    for (int oc = 0; oc < 64; oc++)
        g_feat[(b*CC + oc)*HWP + pix] = acc[oc];
}

// ---------------------------------------------------------------------------
// Kernel 2: offset conv  g_feat -> g_off[4,18,256,256], 3x3 pad 1
// (round-2 form: no occupancy cap — that config measured best)
// ---------------------------------------------------------------------------
__global__ __launch_bounds__(256) void offconv_kernel(
    const float* __restrict__ w, const float* __restrict__ bias)
{
    __shared__ __align__(16) float w_sh[576][20];  // [ic*9+kk][o], padded 18->20
    __shared__ float b_sh[18];
    int tid = threadIdx.x;
    for (int idx = tid; idx < 18*576; idx += 256) {
        int o = idx / 576, r = idx % 576;          // w: [o][ic][ky][kx]
        w_sh[r][o] = w[idx];
    }
    if (tid < 18) b_sh[tid] = bias[tid];
    __syncthreads();

    int px  = blockIdx.x * 256 + tid;
    int b   = px >> 16;
    int rem = px & 0xFFFF;
    int oy  = rem >> 8, ox = rem & 255;

    u64 acc[9];
    #pragma unroll
    for (int j = 0; j < 9; j++) acc[j] = pack2(b_sh[2*j], b_sh[2*j+1]);

    const float* fb = g_feat + b*CC*HWP;
    for (int ic = 0; ic < 64; ic++) {
        const float* p = fb + ic*HWP;
        float v[9];
        #pragma unroll
        for (int ky = 0; ky < 3; ky++)
            #pragma unroll
            for (int kx = 0; kx < 3; kx++) {
                int iy = oy + ky - 1, ix = ox + kx - 1;
                bool ok = (iy >= 0 && iy < HH && ix >= 0 && ix < WW);
                v[ky*3 + kx] = ok ? __ldg(&p[iy*WW + ix]) : 0.f;
            }
        #pragma unroll
        for (int kk = 0; kk < 9; kk++) {
            u64 s2 = pack2(v[kk], v[kk]);
            int r = ic*9 + kk;
            #pragma unroll
            for (int m = 0; m < 4; m++) {
                ulonglong2 wv = *(const ulonglong2*)&w_sh[r][4*m];
                fma2(acc[2*m],   wv.x, s2);
                fma2(acc[2*m+1], wv.y, s2);
            }
            u64 wt = *(const u64*)&w_sh[r][16];
            fma2(acc[8], wt, s2);
        }
    }
    int pix = oy*WW + ox;
    #pragma unroll
    for (int j = 0; j < 9; j++) {
        float lo, hi; unpack2(acc[j], lo, hi);
        g_off[(b*KOFF + 2*j  )*HWP + pix] = lo;
        g_off[(b*KOFF + 2*j+1)*HWP + pix] = hi;
    }
}

// ---------------------------------------------------------------------------
// Kernel 3: deformable conv  (g_feat, g_off) -> out[4,64,256,256]
// k-outer restructure: only the per-k weight slice W_k[64ic][64oc] = 64KB in
// smem -> 2 CTAs/SM (16 warps/SM) instead of 1 CTA. 1 px/thread, FFMA2.
// ---------------------------------------------------------------------------
struct Samp { float w00, w01, w10, w11; int i00, i01, i10, i11; };

__device__ __forceinline__ Samp make_samp(float sy, float sx)
{
    float y0f = floorf(sy), x0f = floorf(sx);
    float dy = sy - y0f,    dx = sx - x0f;

    // per-corner validity on the UNCLIPPED float coordinate (ref semantics)
    bool vy0 = (y0f       >= 0.f) && (y0f       <= (float)(HH-1));
    bool vy1 = (y0f + 1.f >= 0.f) && (y0f + 1.f <= (float)(HH-1));
    bool vx0 = (x0f       >= 0.f) && (x0f       <= (float)(WW-1));
    bool vx1 = (x0f + 1.f >= 0.f) && (x0f + 1.f <= (float)(WW-1));

    int y0 = (int)fminf(fmaxf(y0f,       0.f), (float)(HH-1));
    int y1 = (int)fminf(fmaxf(y0f + 1.f, 0.f), (float)(HH-1));
    int x0 = (int)fminf(fmaxf(x0f,       0.f), (float)(WW-1));
    int x1 = (int)fminf(fmaxf(x0f + 1.f, 0.f), (float)(WW-1));

    Samp s;
    s.w00 = (1.f-dy)*(1.f-dx) * ((vy0 && vx0) ? 1.f : 0.f);
    s.w01 = (1.f-dy)*dx       * ((vy0 && vx1) ? 1.f : 0.f);
    s.w10 = dy*(1.f-dx)       * ((vy1 && vx0) ? 1.f : 0.f);
    s.w11 = dy*dx             * ((vy1 && vx1) ? 1.f : 0.f);
    s.i00 = y0*WW + x0;  s.i01 = y0*WW + x1;
    s.i10 = y1*WW + x0;  s.i11 = y1*WW + x1;
    return s;
}

__global__ __launch_bounds__(256, 2) void deform_kernel(
    const float* __restrict__ dw, const float* __restrict__ dbias,
    float* __restrict__ out)
{
    __shared__ __align__(16) float w_sh[64][64];   // per-k slice: [ic][oc]
    __shared__ float b_sh[64];
    int tid = threadIdx.x;
    if (tid < 64) b_sh[tid] = dbias[tid];

    int px  = blockIdx.x * 256 + tid;
    int b   = px >> 16;
    int rem = px & 0xFFFF;
    int oy  = rem >> 8, ox = rem & 255;
    int pix = oy*WW + ox;

    const float* fb = g_feat + b*CC*HWP;
    const float* ob = g_off  + b*KOFF*HWP;

    // bias init (after the b_sh write, before first use — sync comes inside loop)
    __syncthreads();
    u64 acc[32];
    #pragma unroll
    for (int j = 0; j < 32; j++) acc[j] = pack2(b_sh[2*j], b_sh[2*j+1]);

    #pragma unroll 1
    for (int k = 0; k < 9; k++) {
        // stage W_k[ic][oc] = dw[oc][ic][k]   (dw: [oc][ic][3][3])
        __syncthreads();
        #pragma unroll
        for (int t = 0; t < 16; t++) {
            int idx = tid + t*256;               // 4096 elements
            int ic = idx >> 6, oc = idx & 63;
            w_sh[ic][oc] = __ldg(&dw[(oc*64 + ic)*9 + k]);
        }
        __syncthreads();

        int i = k / 3, j = k % 3;
        float offy = __ldg(ob + (2*k    )*HWP + pix);
        float offx = __ldg(ob + (2*k + 1)*HWP + pix);

        Samp S = make_samp((float)(oy - 1 + i) + offy,
                           (float)(ox - 1 + j) + offx);

        #pragma unroll 2
        for (int ic = 0; ic < 64; ic++) {
            const float* p = fb + ic*HWP;
            float s = S.w00*__ldg(p + S.i00) + S.w01*__ldg(p + S.i01)
                    + S.w10*__ldg(p + S.i10) + S.w11*__ldg(p + S.i11);
            u64 s2 = pack2(s, s);
            const float* wr = &w_sh[ic][0];
            #pragma unroll
            for (int m = 0; m < 8; m++) {
                ulonglong2 wv  = *(const ulonglong2*)(wr + 8*m);
                ulonglong2 wv2 = *(const ulonglong2*)(wr + 8*m + 4);
                fma2(acc[4*m],   wv.x,  s2);
                fma2(acc[4*m+1], wv.y,  s2);
                fma2(acc[4*m+2], wv2.x, s2);
                fma2(acc[4*m+3], wv2.y, s2);
            }
        }
    }

    #pragma unroll
    for (int j = 0; j < 32; j++) {
        float lo, hi; unpack2(acc[j], lo, hi);
        out[(b*CC + 2*j  )*HWP + pix] = lo;
        out[(b*CC + 2*j+1)*HWP + pix] = hi;
    }
}

// ---------------------------------------------------------------------------
extern "C" void kernel_launch(void* const* d_in, const int* in_sizes, int n_in,
                              void* d_out, int out_size)
{
    const float* x      = (const float*)d_in[0];
    const float* conv_w = (const float*)d_in[1];
    const float* conv_b = (const float*)d_in[2];
    const float* off_w  = (const float*)d_in[3];
    const float* off_b  = (const float*)d_in[4];
    const float* dw     = (const float*)d_in[5];
    const float* db     = (const float*)d_in[6];
    float* out = (float*)d_out;

    const int blocks = BB*HH*WW / 256;   // 1024

    conv1_kernel  <<<blocks, 256>>>(x, conv_w, conv_b);
    offconv_kernel<<<blocks, 256>>>(off_w, off_b);
    deform_kernel <<<blocks, 256>>>(dw, db, out);
}

// round 6
// speedup vs baseline: 1.5590x; 1.5590x over previous
#include <cuda_runtime.h>
#include <cuda_bf16.h>
#include <cstdint>

// Problem constants
#define HH 256
#define WW 256
#define BB 4
#define CC 64
#define KOFF 18
#define HWP (HH*WW)

// Scratch (device-global)
__device__ float g_feat[BB*CC*HH*WW];            // 64 MiB
__device__ float g_off [BB*KOFF*HH*WW];          // 18 MiB
__device__ __nv_bfloat16 g_whi[9*64*64];         // deform weights hi, [k][oc][ic]
__device__ __nv_bfloat16 g_wlo[9*64*64];         // deform weights lo

typedef unsigned long long u64;

// ---------------------------------------------------------------------------
// helpers
// ---------------------------------------------------------------------------
__device__ __forceinline__ uint32_t smem_u32(const void* p) {
    uint32_t a;
    asm("{ .reg .u64 t; cvta.to.shared.u64 t, %1; cvt.u32.u64 %0, t; }"
        : "=r"(a) : "l"(p));
    return a;
}
#define SWZ(b) ((b) ^ (((b) >> 3) & 0x70))

__device__ __forceinline__ void ldsm4(uint32_t* r, uint32_t addr) {
    asm volatile("ldmatrix.sync.aligned.m8n8.x4.shared.b16 {%0,%1,%2,%3}, [%4];"
        : "=r"(r[0]), "=r"(r[1]), "=r"(r[2]), "=r"(r[3]) : "r"(addr));
}
__device__ __forceinline__ void mma16816(float* d, const uint32_t* a, const uint32_t* b) {
    asm volatile(
        "mma.sync.aligned.m16n8k16.row.col.f32.bf16.bf16.f32 "
        "{%0,%1,%2,%3}, {%4,%5,%6,%7}, {%8,%9}, {%0,%1,%2,%3};"
        : "+f"(d[0]), "+f"(d[1]), "+f"(d[2]), "+f"(d[3])
        : "r"(a[0]), "r"(a[1]), "r"(a[2]), "r"(a[3]), "r"(b[0]), "r"(b[1]));
}

// Packed f32x2 helpers for offconv
__device__ __forceinline__ void fma2(u64 &d, u64 a, u64 b) {
    asm("fma.rn.f32x2 %0, %1, %2, %0;" : "+l"(d) : "l"(a), "l"(b));
}
__device__ __forceinline__ u64 pack2(float lo, float hi) {
    u64 r; asm("mov.b64 %0, {%1, %2};" : "=l"(r) : "f"(lo), "f"(hi)); return r;
}
__device__ __forceinline__ void unpack2(u64 v, float &lo, float &hi) {
    asm("mov.b64 {%0, %1}, %2;" : "=f"(lo), "=f"(hi) : "l"(v));
}

// ---------------------------------------------------------------------------
// Kernel 1: conv1 (proven: 41.6us)
// ---------------------------------------------------------------------------
__global__ __launch_bounds__(256) void conv1_kernel(
    const float* __restrict__ x, const float* __restrict__ w,
    const float* __restrict__ bias)
{
    __shared__ __align__(16) float w_sh[27][64];
    __shared__ float b_sh[64];
    int tid = threadIdx.x;
    for (int idx = tid; idx < 64*27; idx += 256) {
        int oc = idx / 27, r = idx % 27;
        w_sh[r][oc] = w[idx];
    }
    if (tid < 64) b_sh[tid] = bias[tid];
    __syncthreads();

    int px  = blockIdx.x * 256 + tid;
    int b   = px >> 16;
    int rem = px & 0xFFFF;
    int oy  = rem >> 8, ox = rem & 255;

    float in[27];
    #pragma unroll
    for (int c = 0; c < 3; c++)
        #pragma unroll
        for (int ky = 0; ky < 3; ky++)
            #pragma unroll
            for (int kx = 0; kx < 3; kx++) {
                int iy = oy + ky - 1, ix = ox + kx - 1;
                bool ok = (iy >= 0 && iy < HH && ix >= 0 && ix < WW);
                in[c*9 + ky*3 + kx] = ok ? __ldg(&x[((b*3 + c)*HH + iy)*WW + ix]) : 0.f;
            }

    float acc[64];
    #pragma unroll
    for (int oc = 0; oc < 64; oc++) acc[oc] = b_sh[oc];

    #pragma unroll
    for (int r = 0; r < 27; r++) {
        float v = in[r];
        #pragma unroll
        for (int oc = 0; oc < 64; oc += 4) {
            float4 wv = *(const float4*)&w_sh[r][oc];
            acc[oc+0] += v * wv.x;  acc[oc+1] += v * wv.y;
            acc[oc+2] += v * wv.z;  acc[oc+3] += v * wv.w;
        }
    }
    int pix = oy*WW + ox;
    #pragma unroll
    for (int oc = 0; oc < 64; oc++)
        g_feat[(b*CC + oc)*HWP + pix] = acc[oc];
}

// ---------------------------------------------------------------------------
// Kernel 2: offset conv (round-2 form — best measured)
// ---------------------------------------------------------------------------
__global__ __launch_bounds__(256) void offconv_kernel(
    const float* __restrict__ w, const float* __restrict__ bias)
{
    __shared__ __align__(16) float w_sh[576][20];
    __shared__ float b_sh[18];
    int tid = threadIdx.x;
    for (int idx = tid; idx < 18*576; idx += 256) {
        int o = idx / 576, r = idx % 576;
        w_sh[r][o] = w[idx];
    }
    if (tid < 18) b_sh[tid] = bias[tid];
    __syncthreads();

    int px  = blockIdx.x * 256 + tid;
    int b   = px >> 16;
    int rem = px & 0xFFFF;
    int oy  = rem >> 8, ox = rem & 255;

    u64 acc[9];
    #pragma unroll
    for (int j = 0; j < 9; j++) acc[j] = pack2(b_sh[2*j], b_sh[2*j+1]);

    const float* fb = g_feat + b*CC*HWP;
    for (int ic = 0; ic < 64; ic++) {
        const float* p = fb + ic*HWP;
        float v[9];
        #pragma unroll
        for (int ky = 0; ky < 3; ky++)
            #pragma unroll
            for (int kx = 0; kx < 3; kx++) {
                int iy = oy + ky - 1, ix = ox + kx - 1;
                bool ok = (iy >= 0 && iy < HH && ix >= 0 && ix < WW);
                v[ky*3 + kx] = ok ? __ldg(&p[iy*WW + ix]) : 0.f;
            }
        #pragma unroll
        for (int kk = 0; kk < 9; kk++) {
            u64 s2 = pack2(v[kk], v[kk]);
            int r = ic*9 + kk;
            #pragma unroll
            for (int m = 0; m < 4; m++) {
                ulonglong2 wv = *(const ulonglong2*)&w_sh[r][4*m];
                fma2(acc[2*m],   wv.x, s2);
                fma2(acc[2*m+1], wv.y, s2);
            }
            u64 wt = *(const u64*)&w_sh[r][16];
            fma2(acc[8], wt, s2);
        }
    }
    int pix = oy*WW + ox;
    #pragma unroll
    for (int j = 0; j < 9; j++) {
        float lo, hi; unpack2(acc[j], lo, hi);
        g_off[(b*KOFF + 2*j  )*HWP + pix] = lo;
        g_off[(b*KOFF + 2*j+1)*HWP + pix] = hi;
    }
}

// ---------------------------------------------------------------------------
// Kernel 2.5: convert deform weights fp32 -> split bf16 [k][oc][ic]
// ---------------------------------------------------------------------------
__global__ void wconv_kernel(const float* __restrict__ dw)
{
    int idx = blockIdx.x * 256 + threadIdx.x;
    if (idx >= 9*64*64) return;
    int k = idx >> 12, r = idx & 4095;
    int oc = r >> 6, ic = r & 63;
    float s = dw[(oc*64 + ic)*9 + k];
    __nv_bfloat16 h = __float2bfloat16_rn(s);
    float res = s - __bfloat162float(h);
    g_whi[idx] = h;
    g_wlo[idx] = __float2bfloat16_rn(res);
}

// ---------------------------------------------------------------------------
// Kernel 3: deformable conv — warp-level mma.sync (HMMA), split-bf16
// CTA = 128 px (M) x 64 oc (N); 8 warps, each m16 x n64
// ---------------------------------------------------------------------------
#define BIAS_OFF 0
#define S_HI_OFF 256
#define S_LO_OFF (S_HI_OFF + 16384)    // 16640
#define W_HI_OFF (S_LO_OFF + 16384)    // 33024
#define W_LO_OFF (W_HI_OFF + 8192)     // 41216
#define SMEM3_TOT (W_LO_OFF + 8192)    // 49408

struct Samp { float w00, w01, w10, w11; int i00, i01, i10, i11; };

__device__ __forceinline__ Samp make_samp(float sy, float sx)
{
    float y0f = floorf(sy), x0f = floorf(sx);
    float dy = sy - y0f,    dx = sx - x0f;

    bool vy0 = (y0f       >= 0.f) && (y0f       <= (float)(HH-1));
    bool vy1 = (y0f + 1.f >= 0.f) && (y0f + 1.f <= (float)(HH-1));
    bool vx0 = (x0f       >= 0.f) && (x0f       <= (float)(WW-1));
    bool vx1 = (x0f + 1.f >= 0.f) && (x0f + 1.f <= (float)(WW-1));

    int y0 = (int)fminf(fmaxf(y0f,       0.f), (float)(HH-1));
    int y1 = (int)fminf(fmaxf(y0f + 1.f, 0.f), (float)(HH-1));
    int x0 = (int)fminf(fmaxf(x0f,       0.f), (float)(WW-1));
    int x1 = (int)fminf(fmaxf(x0f + 1.f, 0.f), (float)(WW-1));

    Samp s;
    s.w00 = (1.f-dy)*(1.f-dx) * ((vy0 && vx0) ? 1.f : 0.f);
    s.w01 = (1.f-dy)*dx       * ((vy0 && vx1) ? 1.f : 0.f);
    s.w10 = dy*(1.f-dx)       * ((vy1 && vx0) ? 1.f : 0.f);
    s.w11 = dy*dx             * ((vy1 && vx1) ? 1.f : 0.f);
    s.i00 = y0*WW + x0;  s.i01 = y0*WW + x1;
    s.i10 = y1*WW + x0;  s.i11 = y1*WW + x1;
    return s;
}

__global__ __launch_bounds__(256, 2) void deform_mma_kernel(
    const float* __restrict__ dbias, float* __restrict__ out)
{
    extern __shared__ char smem[];
    uint32_t sb = smem_u32(smem);
    int tid = threadIdx.x;
    int wid = tid >> 5, lane = tid & 31;

    if (tid < 64) ((float*)(smem + BIAS_OFF))[tid] = __ldg(&dbias[tid]);

    int px0 = blockIdx.x * 128;
    int b   = px0 >> 16;
    int rem = px0 & 0xFFFF;
    int oy  = rem >> 8, ox_base = rem & 255;

    int px_local = tid >> 1;            // 0..127
    int ic0      = (tid & 1) * 32;      // 0 or 32
    int ox       = ox_base + px_local;
    int pix      = oy*WW + ox;

    const float* fb = g_feat + b*CC*HWP;
    const float* ob = g_off  + b*KOFF*HWP;

    // per-lane ldmatrix address components
    uint32_t a_row  = (uint32_t)(wid*16 + (lane & 15)) * 128;   // A row byte
    uint32_t a_col  = (uint32_t)((lane >> 4) * 16);
    uint32_t b_row  = (uint32_t)(((lane >> 4) & 1)*8 + (lane & 7)) * 128;  // within n-pair
    uint32_t b_col  = (uint32_t)(((lane >> 3) & 1) * 16);

    float acc[32];
    #pragma unroll
    for (int i = 0; i < 32; i++) acc[i] = 0.f;

    #pragma unroll 1
    for (int k = 0; k < 9; k++) {
        __syncthreads();   // protect smem from prior tap's readers

        // ---- stage W_k hi/lo: [oc][ic] bf16, SWZ swizzled (2048 u32 each) ----
        {
            const uint32_t* whik = (const uint32_t*)g_whi + k*2048;
            const uint32_t* wlok = (const uint32_t*)g_wlo + k*2048;
            #pragma unroll
            for (int t = 0; t < 8; t++) {
                int idx = tid + t*256;
                uint32_t sw = SWZ((uint32_t)idx * 4);
                *(uint32_t*)(smem + W_HI_OFF + sw) = __ldg(whik + idx);
                *(uint32_t*)(smem + W_LO_OFF + sw) = __ldg(wlok + idx);
            }
        }

        // ---- build S chunk: this thread's 32 ic for its pixel ----
        int i = k / 3, j = k % 3;
        float offy = __ldg(ob + (2*k    )*HWP + pix);
        float offx = __ldg(ob + (2*k + 1)*HWP + pix);
        Samp S = make_samp((float)(oy - 1 + i) + offy,
                           (float)(ox - 1 + j) + offx);

        #pragma unroll 4
        for (int t = 0; t < 16; t++) {
            int ic = ic0 + t*2;
            const float* p0 = fb + ic*HWP;
            const float* p1 = p0 + HWP;
            float s0 = S.w00*__ldg(p0 + S.i00) + S.w01*__ldg(p0 + S.i01)
                     + S.w10*__ldg(p0 + S.i10) + S.w11*__ldg(p0 + S.i11);
            float s1 = S.w00*__ldg(p1 + S.i00) + S.w01*__ldg(p1 + S.i01)
                     + S.w10*__ldg(p1 + S.i10) + S.w11*__ldg(p1 + S.i11);
            __nv_bfloat16 h0 = __float2bfloat16_rn(s0);
            __nv_bfloat16 h1 = __float2bfloat16_rn(s1);
            __nv_bfloat16 l0 = __float2bfloat16_rn(s0 - __bfloat162float(h0));
            __nv_bfloat16 l1 = __float2bfloat16_rn(s1 - __bfloat162float(h1));
            uint32_t sw = SWZ((uint32_t)(px_local*128 + ic*2));
            *(__nv_bfloat162*)(smem + S_HI_OFF + sw) = __halves2bfloat162(h0, h1);
            *(__nv_bfloat162*)(smem + S_LO_OFF + sw) = __halves2bfloat162(l0, l1);
        }

        __syncthreads();

        // ---- MMA: (A_hi+A_lo)·W_hi, then A_hi·W_lo ----
        #pragma unroll
        for (int ks = 0; ks < 4; ks++) {
            uint32_t aH[4], aL[4];
            uint32_t acol = (uint32_t)(ks*32) + a_col;
            ldsm4(aH, sb + S_HI_OFF + SWZ(a_row + acol));
            ldsm4(aL, sb + S_LO_OFF + SWZ(a_row + acol));
            #pragma unroll
            for (int nt = 0; nt < 4; nt++) {
                uint32_t bf[4];
                uint32_t baddr = sb + W_HI_OFF
                               + SWZ((uint32_t)(nt*16)*128 + b_row + (uint32_t)(ks*32) + b_col);
                ldsm4(bf, baddr);
                mma16816(acc + nt*8,     aH, bf);
                mma16816(acc + nt*8 + 4, aH, bf + 2);
                mma16816(acc + nt*8,     aL, bf);
                mma16816(acc + nt*8 + 4, aL, bf + 2);
            }
        }
        #pragma unroll
        for (int ks = 0; ks < 4; ks++) {
            uint32_t aH[4];
            uint32_t acol = (uint32_t)(ks*32) + a_col;
            ldsm4(aH, sb + S_HI_OFF + SWZ(a_row + acol));
            #pragma unroll
            for (int nt = 0; nt < 4; nt++) {
                uint32_t bf[4];
                uint32_t baddr = sb + W_LO_OFF
                               + SWZ((uint32_t)(nt*16)*128 + b_row + (uint32_t)(ks*32) + b_col);
                ldsm4(bf, baddr);
                mma16816(acc + nt*8,     aH, bf);
                mma16816(acc + nt*8 + 4, aH, bf + 2);
            }
        }
    }

    // ---- epilogue: D frags -> smem [oc][px] (132-float rows) -> coalesced out
    __syncthreads();
    float* ds = (float*)(smem + S_HI_OFF);     // 64*132 floats = 33792 B
    {
        int pxr = wid*16 + (lane >> 2);
        int occ = 2*(lane & 3);
        #pragma unroll
        for (int nt2 = 0; nt2 < 8; nt2++) {
            int oc = nt2*8 + occ;
            ds[ oc   *132 + pxr    ] = acc[nt2*4+0];
            ds[(oc+1)*132 + pxr    ] = acc[nt2*4+1];
            ds[ oc   *132 + pxr + 8] = acc[nt2*4+2];
            ds[(oc+1)*132 + pxr + 8] = acc[nt2*4+3];
        }
    }
    __syncthreads();
    {
        const float* bs = (const float*)(smem + BIAS_OFF);
        int opix0 = oy*WW + ox_base;
        #pragma unroll
        for (int t = 0; t < 8; t++) {
            int oc = wid*8 + t;
            float bv = bs[oc];
            float4 v = *(const float4*)&ds[oc*132 + lane*4];
            v.x += bv; v.y += bv; v.z += bv; v.w += bv;
            *(float4*)&out[(b*CC + oc)*HWP + opix0 + lane*4] = v;
        }
    }
}

// ---------------------------------------------------------------------------
extern "C" void kernel_launch(void* const* d_in, const int* in_sizes, int n_in,
                              void* d_out, int out_size)
{
    const float* x      = (const float*)d_in[0];
    const float* conv_w = (const float*)d_in[1];
    const float* conv_b = (const float*)d_in[2];
    const float* off_w  = (const float*)d_in[3];
    const float* off_b  = (const float*)d_in[4];
    const float* dw     = (const float*)d_in[5];
    const float* db     = (const float*)d_in[6];
    float* out = (float*)d_out;

    const int blocks = BB*HH*WW / 256;   // 1024

    wconv_kernel  <<<144, 256>>>(dw);
    conv1_kernel  <<<blocks, 256>>>(x, conv_w, conv_b);
    offconv_kernel<<<blocks, 256>>>(off_w, off_b);

    cudaFuncSetAttribute(deform_mma_kernel,
                         cudaFuncAttributeMaxDynamicSharedMemorySize, SMEM3_TOT);
    deform_mma_kernel<<<BB*HH*WW/128, 256, SMEM3_TOT>>>(db, out);
}

// round 7
// speedup vs baseline: 2.0909x; 1.3412x over previous
#include <cuda_runtime.h>
#include <cuda_bf16.h>
#include <cstdint>

// Problem constants
#define HH 256
#define WW 256
#define BB 4
#define CC 64
#define KOFF 18
#define HWP (HH*WW)

// Scratch (device-global)
__device__ float g_feat[BB*CC*HH*WW];            // 64 MiB
__device__ float g_off [BB*KOFF*HH*WW];          // 18 MiB
// deform weights in per-lane HMMA fragment order:
// idx(k,ks,ntp,l,r) = (((k*4+ks)*4+ntp)*32 + l)*4 + r
__device__ uint32_t g_wfragH[9*4*4*32*4];
__device__ uint32_t g_wfragL[9*4*4*32*4];

typedef unsigned long long u64;

// ---------------------------------------------------------------------------
// helpers
// ---------------------------------------------------------------------------
__device__ __forceinline__ uint32_t smem_u32(const void* p) {
    uint32_t a;
    asm("{ .reg .u64 t; cvta.to.shared.u64 t, %1; cvt.u32.u64 %0, t; }"
        : "=r"(a) : "l"(p));
    return a;
}
#define SWZ(b) ((b) ^ (((b) >> 3) & 0x70))

__device__ __forceinline__ void ldsm4(uint32_t* r, uint32_t addr) {
    asm volatile("ldmatrix.sync.aligned.m8n8.x4.shared.b16 {%0,%1,%2,%3}, [%4];"
        : "=r"(r[0]), "=r"(r[1]), "=r"(r[2]), "=r"(r[3]) : "r"(addr));
}
__device__ __forceinline__ void mma16816(float* d, const uint32_t* a, const uint32_t* b) {
    asm volatile(
        "mma.sync.aligned.m16n8k16.row.col.f32.bf16.bf16.f32 "
        "{%0,%1,%2,%3}, {%4,%5,%6,%7}, {%8,%9}, {%0,%1,%2,%3};"
        : "+f"(d[0]), "+f"(d[1]), "+f"(d[2]), "+f"(d[3])
        : "r"(a[0]), "r"(a[1]), "r"(a[2]), "r"(a[3]), "r"(b[0]), "r"(b[1]));
}

// Packed f32x2 helpers for offconv
__device__ __forceinline__ void fma2(u64 &d, u64 a, u64 b) {
    asm("fma.rn.f32x2 %0, %1, %2, %0;" : "+l"(d) : "l"(a), "l"(b));
}
__device__ __forceinline__ u64 pack2(float lo, float hi) {
    u64 r; asm("mov.b64 %0, {%1, %2};" : "=l"(r) : "f"(lo), "f"(hi)); return r;
}
__device__ __forceinline__ void unpack2(u64 v, float &lo, float &hi) {
    asm("mov.b64 {%0, %1}, %2;" : "=f"(lo), "=f"(hi) : "l"(v));
}

// ---------------------------------------------------------------------------
// Kernel 1: conv1 (proven: 41.6us)
// ---------------------------------------------------------------------------
__global__ __launch_bounds__(256) void conv1_kernel(
    const float* __restrict__ x, const float* __restrict__ w,
    const float* __restrict__ bias)
{
    __shared__ __align__(16) float w_sh[27][64];
    __shared__ float b_sh[64];
    int tid = threadIdx.x;
    for (int idx = tid; idx < 64*27; idx += 256) {
        int oc = idx / 27, r = idx % 27;
        w_sh[r][oc] = w[idx];
    }
    if (tid < 64) b_sh[tid] = bias[tid];
    __syncthreads();

    int px  = blockIdx.x * 256 + tid;
    int b   = px >> 16;
    int rem = px & 0xFFFF;
    int oy  = rem >> 8, ox = rem & 255;

    float in[27];
    #pragma unroll
    for (int c = 0; c < 3; c++)
        #pragma unroll
        for (int ky = 0; ky < 3; ky++)
            #pragma unroll
            for (int kx = 0; kx < 3; kx++) {
                int iy = oy + ky - 1, ix = ox + kx - 1;
                bool ok = (iy >= 0 && iy < HH && ix >= 0 && ix < WW);
                in[c*9 + ky*3 + kx] = ok ? __ldg(&x[((b*3 + c)*HH + iy)*WW + ix]) : 0.f;
            }

    float acc[64];
    #pragma unroll
    for (int oc = 0; oc < 64; oc++) acc[oc] = b_sh[oc];

    #pragma unroll
    for (int r = 0; r < 27; r++) {
        float v = in[r];
        #pragma unroll
        for (int oc = 0; oc < 64; oc += 4) {
            float4 wv = *(const float4*)&w_sh[r][oc];
            acc[oc+0] += v * wv.x;  acc[oc+1] += v * wv.y;
            acc[oc+2] += v * wv.z;  acc[oc+3] += v * wv.w;
        }
    }
    int pix = oy*WW + ox;
    #pragma unroll
    for (int oc = 0; oc < 64; oc++)
        g_feat[(b*CC + oc)*HWP + pix] = acc[oc];
}

// ---------------------------------------------------------------------------
// Kernel 2: offset conv (round-2 form — best measured)
// ---------------------------------------------------------------------------
__global__ __launch_bounds__(256) void offconv_kernel(
    const float* __restrict__ w, const float* __restrict__ bias)
{
    __shared__ __align__(16) float w_sh[576][20];
    __shared__ float b_sh[18];
    int tid = threadIdx.x;
    for (int idx = tid; idx < 18*576; idx += 256) {
        int o = idx / 576, r = idx % 576;
        w_sh[r][o] = w[idx];
    }
    if (tid < 18) b_sh[tid] = bias[tid];
    __syncthreads();

    int px  = blockIdx.x * 256 + tid;
    int b   = px >> 16;
    int rem = px & 0xFFFF;
    int oy  = rem >> 8, ox = rem & 255;

    u64 acc[9];
    #pragma unroll
    for (int j = 0; j < 9; j++) acc[j] = pack2(b_sh[2*j], b_sh[2*j+1]);

    const float* fb = g_feat + b*CC*HWP;
    for (int ic = 0; ic < 64; ic++) {
        const float* p = fb + ic*HWP;
        float v[9];
        #pragma unroll
        for (int ky = 0; ky < 3; ky++)
            #pragma unroll
            for (int kx = 0; kx < 3; kx++) {
                int iy = oy + ky - 1, ix = ox + kx - 1;
                bool ok = (iy >= 0 && iy < HH && ix >= 0 && ix < WW);
                v[ky*3 + kx] = ok ? __ldg(&p[iy*WW + ix]) : 0.f;
            }
        #pragma unroll
        for (int kk = 0; kk < 9; kk++) {
            u64 s2 = pack2(v[kk], v[kk]);
            int r = ic*9 + kk;
            #pragma unroll
            for (int m = 0; m < 4; m++) {
                ulonglong2 wv = *(const ulonglong2*)&w_sh[r][4*m];
                fma2(acc[2*m],   wv.x, s2);
                fma2(acc[2*m+1], wv.y, s2);
            }
            u64 wt = *(const u64*)&w_sh[r][16];
            fma2(acc[8], wt, s2);
        }
    }
    int pix = oy*WW + ox;
    #pragma unroll
    for (int j = 0; j < 9; j++) {
        float lo, hi; unpack2(acc[j], lo, hi);
        g_off[(b*KOFF + 2*j  )*HWP + pix] = lo;
        g_off[(b*KOFF + 2*j+1)*HWP + pix] = hi;
    }
}

// ---------------------------------------------------------------------------
// Kernel 2.5: build per-lane HMMA B fragments from deform weights (split bf16)
// B[k][n] = W[n][k]; lane l of (k-tap, ks, nt) holds
//   reg0 = (W[n][c], W[n][c+1]),  reg1 = (W[n][c+8], W[n][c+9])
//   n = nt*8 + l/4,  c = 2*(l%4) + 16*ks  (reg1: +8)
// stored LDG.128-friendly: [k][ks][ntp][l][4] with nt = 2*ntp + r/2
// ---------------------------------------------------------------------------
__global__ void wfrag_kernel(const float* __restrict__ dw)
{
    int idx = blockIdx.x * 256 + threadIdx.x;   // one thread per u32 slot
    if (idx >= 9*4*4*32*4) return;
    int r    = idx & 3;
    int l    = (idx >> 2) & 31;
    int ntp  = (idx >> 7) & 3;
    int ks   = (idx >> 9) & 3;
    int k    = idx >> 11;
    int nt   = ntp*2 + (r >> 1);
    int n    = nt*8 + (l >> 2);
    int c    = 2*(l & 3) + (r & 1)*8 + 16*ks;

    float w0 = dw[(n*64 + c    )*9 + k];
    float w1 = dw[(n*64 + c + 1)*9 + k];
    __nv_bfloat16 h0 = __float2bfloat16_rn(w0);
    __nv_bfloat16 h1 = __float2bfloat16_rn(w1);
    __nv_bfloat16 l0 = __float2bfloat16_rn(w0 - __bfloat162float(h0));
    __nv_bfloat16 l1 = __float2bfloat16_rn(w1 - __bfloat162float(h1));
    __nv_bfloat162 ph = __halves2bfloat162(h0, h1);
    __nv_bfloat162 pl = __halves2bfloat162(l0, l1);
    g_wfragH[idx] = *(uint32_t*)&ph;
    g_wfragL[idx] = *(uint32_t*)&pl;
}

// ---------------------------------------------------------------------------
// Kernel 3: deformable conv — HMMA, CTA = one image row (256 px), 8 warps m32n64
// S hi/lo in smem; B operands loaded as pre-built fragments straight from global.
// ---------------------------------------------------------------------------
#define S_HI_OFF 0
#define S_LO_OFF 32768
#define BIAS_OFF 66560                 // above the 64x260 f32 epilogue area
#define SMEM3_TOT (66560 + 256)        // 66816

struct Samp { float w00, w01, w10, w11; int i00, i01, i10, i11; };

__device__ __forceinline__ Samp make_samp(float sy, float sx)
{
    float y0f = floorf(sy), x0f = floorf(sx);
    float dy = sy - y0f,    dx = sx - x0f;

    bool vy0 = (y0f       >= 0.f) && (y0f       <= (float)(HH-1));
    bool vy1 = (y0f + 1.f >= 0.f) && (y0f + 1.f <= (float)(HH-1));
    bool vx0 = (x0f       >= 0.f) && (x0f       <= (float)(WW-1));
    bool vx1 = (x0f + 1.f >= 0.f) && (x0f + 1.f <= (float)(WW-1));

    int y0 = (int)fminf(fmaxf(y0f,       0.f), (float)(HH-1));
    int y1 = (int)fminf(fmaxf(y0f + 1.f, 0.f), (float)(HH-1));
    int x0 = (int)fminf(fmaxf(x0f,       0.f), (float)(WW-1));
    int x1 = (int)fminf(fmaxf(x0f + 1.f, 0.f), (float)(WW-1));

    Samp s;
    s.w00 = (1.f-dy)*(1.f-dx) * ((vy0 && vx0) ? 1.f : 0.f);
    s.w01 = (1.f-dy)*dx       * ((vy0 && vx1) ? 1.f : 0.f);
    s.w10 = dy*(1.f-dx)       * ((vy1 && vx0) ? 1.f : 0.f);
    s.w11 = dy*dx             * ((vy1 && vx1) ? 1.f : 0.f);
    s.i00 = y0*WW + x0;  s.i01 = y0*WW + x1;
    s.i10 = y1*WW + x0;  s.i11 = y1*WW + x1;
    return s;
}

__global__ __launch_bounds__(256, 2) void deform_mma_kernel(
    const float* __restrict__ dbias, float* __restrict__ out)
{
    extern __shared__ char smem[];
    uint32_t sb = smem_u32(smem);
    int tid = threadIdx.x;
    int wid = tid >> 5, lane = tid & 31;

    if (tid < 64) ((float*)(smem + BIAS_OFF))[tid] = __ldg(&dbias[tid]);

    int b  = blockIdx.x >> 8;
    int oy = blockIdx.x & 255;
    int ox = tid;                       // 1 thread = 1 pixel of this row
    int pix = oy*WW + ox;

    const float* fb = g_feat + b*CC*HWP;
    const float* ob = g_off  + b*KOFF*HWP;

    float acc[64];                      // [mt2][nt8][4]
    #pragma unroll
    for (int i = 0; i < 64; i++) acc[i] = 0.f;

    // ldmatrix per-lane address components (two m16 tiles per warp)
    uint32_t arow0 = (uint32_t)(wid*32 + (lane & 15)) * 128;
    uint32_t arow1 = arow0 + 16*128;
    uint32_t acol  = (uint32_t)((lane >> 4) * 16);

    #pragma unroll 1
    for (int k = 0; k < 9; k++) {
        __syncthreads();                // prior tap's LDSM readers done

        int i = k / 3, j = k % 3;
        float offy = __ldg(ob + (2*k    )*HWP + pix);
        float offx = __ldg(ob + (2*k + 1)*HWP + pix);
        Samp S = make_samp((float)(oy - 1 + i) + offy,
                           (float)(ox - 1 + j) + offx);

        // gather 64 ic for this pixel, split-bf16, store own 128B smem row
        #pragma unroll 2
        for (int g = 0; g < 16; g++) {
            int ic = g*4;
            float s[4];
            #pragma unroll
            for (int t = 0; t < 4; t++) {
                const float* p = fb + (ic + t)*HWP;
                s[t] = S.w00*__ldg(p + S.i00) + S.w01*__ldg(p + S.i01)
                     + S.w10*__ldg(p + S.i10) + S.w11*__ldg(p + S.i11);
            }
            __nv_bfloat16 h0 = __float2bfloat16_rn(s[0]);
            __nv_bfloat16 h1 = __float2bfloat16_rn(s[1]);
            __nv_bfloat16 h2 = __float2bfloat16_rn(s[2]);
            __nv_bfloat16 h3 = __float2bfloat16_rn(s[3]);
            __nv_bfloat16 q0 = __float2bfloat16_rn(s[0] - __bfloat162float(h0));
            __nv_bfloat16 q1 = __float2bfloat16_rn(s[1] - __bfloat162float(h1));
            __nv_bfloat16 q2 = __float2bfloat16_rn(s[2] - __bfloat162float(h2));
            __nv_bfloat16 q3 = __float2bfloat16_rn(s[3] - __bfloat162float(h3));
            __nv_bfloat162 hA = __halves2bfloat162(h0, h1);
            __nv_bfloat162 hB = __halves2bfloat162(h2, h3);
            __nv_bfloat162 lA = __halves2bfloat162(q0, q1);
            __nv_bfloat162 lB = __halves2bfloat162(q2, q3);
            uint32_t sw = SWZ((uint32_t)(ox*128 + ic*2));   // 8B-aligned, SWZ keeps it
            *(uint2*)(smem + S_HI_OFF + sw) =
                make_uint2(*(uint32_t*)&hA, *(uint32_t*)&hB);
            *(uint2*)(smem + S_LO_OFF + sw) =
                make_uint2(*(uint32_t*)&lA, *(uint32_t*)&lB);
        }

        __syncthreads();

        // MMA: 3-pass split-bf16, B frags straight from global (frag-linear)
        #pragma unroll
        for (int ks = 0; ks < 4; ks++) {
            uint32_t kb = (uint32_t)(ks*32);
            uint32_t aH0[4], aH1[4], aL0[4], aL1[4];
            ldsm4(aH0, sb + S_HI_OFF + SWZ(arow0 + kb + acol));
            ldsm4(aH1, sb + S_HI_OFF + SWZ(arow1 + kb + acol));
            ldsm4(aL0, sb + S_LO_OFF + SWZ(arow0 + kb + acol));
            ldsm4(aL1, sb + S_LO_OFF + SWZ(arow1 + kb + acol));
            #pragma unroll
            for (int ntp = 0; ntp < 4; ntp++) {
                int fidx = (((k*4 + ks)*4 + ntp)*32 + lane)*4;
                uint4 bhv = *(const uint4*)&g_wfragH[fidx];
                uint4 blv = *(const uint4*)&g_wfragL[fidx];
                uint32_t bh[4] = {bhv.x, bhv.y, bhv.z, bhv.w};
                uint32_t bl[4] = {blv.x, blv.y, blv.z, blv.w};
                float* c00 = acc + (0*8 + 2*ntp    )*4;
                float* c10 = acc + (1*8 + 2*ntp    )*4;
                float* c01 = acc + (0*8 + 2*ntp + 1)*4;
                float* c11 = acc + (1*8 + 2*ntp + 1)*4;
                mma16816(c00, aH0, bh);     mma16816(c10, aH1, bh);
                mma16816(c01, aH0, bh + 2); mma16816(c11, aH1, bh + 2);
                mma16816(c00, aL0, bh);     mma16816(c10, aL1, bh);
                mma16816(c01, aL0, bh + 2); mma16816(c11, aL1, bh + 2);
                mma16816(c00, aH0, bl);     mma16816(c10, aH1, bl);
                mma16816(c01, aH0, bl + 2); mma16816(c11, aH1, bl + 2);
            }
        }
    }

    // ---- epilogue: frags -> smem [oc][px] (260-pad) -> coalesced stores ----
    __syncthreads();
    float* ds = (float*)smem;           // 64 x 260 floats
    {
        int mrow = wid*32 + (lane >> 2);
        int ncol = 2*(lane & 3);
        #pragma unroll
        for (int mt = 0; mt < 2; mt++) {
            int m = mrow + mt*16;
            #pragma unroll
            for (int nt = 0; nt < 8; nt++) {
                int n = nt*8 + ncol;
                const float* c = acc + (mt*8 + nt)*4;
                ds[ n   *260 + m    ] = c[0];
                ds[(n+1)*260 + m    ] = c[1];
                ds[ n   *260 + m + 8] = c[2];
                ds[(n+1)*260 + m + 8] = c[3];
            }
        }
    }
    __syncthreads();
    {
        const float* bs = (const float*)(smem + BIAS_OFF);
        int row_base = oy*WW;
        #pragma unroll
        for (int t = 0; t < 8; t++) {
            int oc = wid*8 + t;
            float bv = bs[oc];
            #pragma unroll
            for (int h = 0; h < 2; h++) {
                int p4 = h*128 + lane*4;
                float4 v = *(const float4*)&ds[oc*260 + p4];
                v.x += bv; v.y += bv; v.z += bv; v.w += bv;
                *(float4*)&out[(b*CC + oc)*HWP + row_base + p4] = v;
            }
        }
    }
}

// ---------------------------------------------------------------------------
extern "C" void kernel_launch(void* const* d_in, const int* in_sizes, int n_in,
                              void* d_out, int out_size)
{
    const float* x      = (const float*)d_in[0];
    const float* conv_w = (const float*)d_in[1];
    const float* conv_b = (const float*)d_in[2];
    const float* off_w  = (const float*)d_in[3];
    const float* off_b  = (const float*)d_in[4];
    const float* dw     = (const float*)d_in[5];
    const float* db     = (const float*)d_in[6];
    float* out = (float*)d_out;

    const int blocks = BB*HH*WW / 256;   // 1024

    wfrag_kernel  <<<72, 256>>>(dw);
    conv1_kernel  <<<blocks, 256>>>(x, conv_w, conv_b);
    offconv_kernel<<<blocks, 256>>>(off_w, off_b);

    cudaFuncSetAttribute(deform_mma_kernel,
                         cudaFuncAttributeMaxDynamicSharedMemorySize, SMEM3_TOT);
    deform_mma_kernel<<<BB*HH, 256, SMEM3_TOT>>>(db, out);
}

// round 8
// speedup vs baseline: 2.1909x; 1.0478x over previous
#include <cuda_runtime.h>
#include <cuda_bf16.h>
#include <cstdint>

// Problem constants
#define HH 256
#define WW 256
#define BB 4
#define CC 64
#define KOFF 18
#define HWP (HH*WW)

// Scratch (device-global)
__device__ float g_feat[BB*CC*HH*WW];            // 64 MiB
__device__ float g_off [BB*KOFF*HH*WW];          // 18 MiB
// deform weights in per-lane HMMA fragment order:
// idx(k,ks,ntp,l,r) = (((k*4+ks)*4+ntp)*32 + l)*4 + r
__device__ uint32_t g_wfragH[9*4*4*32*4];
__device__ uint32_t g_wfragL[9*4*4*32*4];
// offset-conv weights, frag order (N padded 18->32):
// idx(k,ks,ntp,l,r) = (((k*4+ks)*2+ntp)*32 + l)*4 + r
__device__ uint32_t g_ofragH[9*4*2*32*4];
__device__ uint32_t g_ofragL[9*4*2*32*4];

typedef unsigned long long u64;

// ---------------------------------------------------------------------------
// helpers
// ---------------------------------------------------------------------------
__device__ __forceinline__ uint32_t smem_u32(const void* p) {
    uint32_t a;
    asm("{ .reg .u64 t; cvta.to.shared.u64 t, %1; cvt.u32.u64 %0, t; }"
        : "=r"(a) : "l"(p));
    return a;
}
#define SWZ(b) ((b) ^ (((b) >> 3) & 0x70))

__device__ __forceinline__ void ldsm4(uint32_t* r, uint32_t addr) {
    asm volatile("ldmatrix.sync.aligned.m8n8.x4.shared.b16 {%0,%1,%2,%3}, [%4];"
        : "=r"(r[0]), "=r"(r[1]), "=r"(r[2]), "=r"(r[3]) : "r"(addr));
}
__device__ __forceinline__ void mma16816(float* d, const uint32_t* a, const uint32_t* b) {
    asm volatile(
        "mma.sync.aligned.m16n8k16.row.col.f32.bf16.bf16.f32 "
        "{%0,%1,%2,%3}, {%4,%5,%6,%7}, {%8,%9}, {%0,%1,%2,%3};"
        : "+f"(d[0]), "+f"(d[1]), "+f"(d[2]), "+f"(d[3])
        : "r"(a[0]), "r"(a[1]), "r"(a[2]), "r"(a[3]), "r"(b[0]), "r"(b[1]));
}

// ---------------------------------------------------------------------------
// Kernel 1: conv1 (proven: 41.6us)
// ---------------------------------------------------------------------------
__global__ __launch_bounds__(256) void conv1_kernel(
    const float* __restrict__ x, const float* __restrict__ w,
    const float* __restrict__ bias)
{
    __shared__ __align__(16) float w_sh[27][64];
    __shared__ float b_sh[64];
    int tid = threadIdx.x;
    for (int idx = tid; idx < 64*27; idx += 256) {
        int oc = idx / 27, r = idx % 27;
        w_sh[r][oc] = w[idx];
    }
    if (tid < 64) b_sh[tid] = bias[tid];
    __syncthreads();

    int px  = blockIdx.x * 256 + tid;
    int b   = px >> 16;
    int rem = px & 0xFFFF;
    int oy  = rem >> 8, ox = rem & 255;

    float in[27];
    #pragma unroll
    for (int c = 0; c < 3; c++)
        #pragma unroll
        for (int ky = 0; ky < 3; ky++)
            #pragma unroll
            for (int kx = 0; kx < 3; kx++) {
                int iy = oy + ky - 1, ix = ox + kx - 1;
                bool ok = (iy >= 0 && iy < HH && ix >= 0 && ix < WW);
                in[c*9 + ky*3 + kx] = ok ? __ldg(&x[((b*3 + c)*HH + iy)*WW + ix]) : 0.f;
            }

    float acc[64];
    #pragma unroll
    for (int oc = 0; oc < 64; oc++) acc[oc] = b_sh[oc];

    #pragma unroll
    for (int r = 0; r < 27; r++) {
        float v = in[r];
        #pragma unroll
        for (int oc = 0; oc < 64; oc += 4) {
            float4 wv = *(const float4*)&w_sh[r][oc];
            acc[oc+0] += v * wv.x;  acc[oc+1] += v * wv.y;
            acc[oc+2] += v * wv.z;  acc[oc+3] += v * wv.w;
        }
    }
    int pix = oy*WW + ox;
    #pragma unroll
    for (int oc = 0; oc < 64; oc++)
        g_feat[(b*CC + oc)*HWP + pix] = acc[oc];
}

// ---------------------------------------------------------------------------
// Kernel 1.5a: build deform B fragments (split bf16), frag-linear
// ---------------------------------------------------------------------------
__global__ void wfrag_kernel(const float* __restrict__ dw)
{
    int idx = blockIdx.x * 256 + threadIdx.x;
    if (idx >= 9*4*4*32*4) return;
    int r    = idx & 3;
    int l    = (idx >> 2) & 31;
    int ntp  = (idx >> 7) & 3;
    int ks   = (idx >> 9) & 3;
    int k    = idx >> 11;
    int nt   = ntp*2 + (r >> 1);
    int n    = nt*8 + (l >> 2);
    int c    = 2*(l & 3) + (r & 1)*8 + 16*ks;

    float w0 = dw[(n*64 + c    )*9 + k];
    float w1 = dw[(n*64 + c + 1)*9 + k];
    __nv_bfloat16 h0 = __float2bfloat16_rn(w0);
    __nv_bfloat16 h1 = __float2bfloat16_rn(w1);
    __nv_bfloat16 l0 = __float2bfloat16_rn(w0 - __bfloat162float(h0));
    __nv_bfloat16 l1 = __float2bfloat16_rn(w1 - __bfloat162float(h1));
    __nv_bfloat162 ph = __halves2bfloat162(h0, h1);
    __nv_bfloat162 pl = __halves2bfloat162(l0, l1);
    g_wfragH[idx] = *(uint32_t*)&ph;
    g_wfragL[idx] = *(uint32_t*)&pl;
}

// ---------------------------------------------------------------------------
// Kernel 1.5b: build offset-conv B fragments (N padded to 32 with zeros)
// ---------------------------------------------------------------------------
__global__ void ofrag_kernel(const float* __restrict__ ow)
{
    int idx = blockIdx.x * 256 + threadIdx.x;
    if (idx >= 9*4*2*32*4) return;
    int r    = idx & 3;
    int l    = (idx >> 2) & 31;
    int ntp  = (idx >> 7) & 1;
    int ks   = (idx >> 8) & 3;
    int k    = idx >> 10;
    int nt   = ntp*2 + (r >> 1);
    int n    = nt*8 + (l >> 2);
    int c    = 2*(l & 3) + (r & 1)*8 + 16*ks;

    float w0 = (n < KOFF) ? ow[(n*64 + c    )*9 + k] : 0.f;
    float w1 = (n < KOFF) ? ow[(n*64 + c + 1)*9 + k] : 0.f;
    __nv_bfloat16 h0 = __float2bfloat16_rn(w0);
    __nv_bfloat16 h1 = __float2bfloat16_rn(w1);
    __nv_bfloat16 l0 = __float2bfloat16_rn(w0 - __bfloat162float(h0));
    __nv_bfloat16 l1 = __float2bfloat16_rn(w1 - __bfloat162float(h1));
    __nv_bfloat162 ph = __halves2bfloat162(h0, h1);
    __nv_bfloat162 pl = __halves2bfloat162(l0, l1);
    g_ofragH[idx] = *(uint32_t*)&ph;
    g_ofragL[idx] = *(uint32_t*)&pl;
}

// ---------------------------------------------------------------------------
// Kernel 2: offset conv — HMMA implicit GEMM (M=256 row px, N=32pad, K=576)
// ---------------------------------------------------------------------------
#define OS_HI 0
#define OS_LO 32768
#define OBIAS_OFF 65536
#define OSMEM_TOT (65536 + 128)

__global__ __launch_bounds__(256, 2) void offconv_mma_kernel(
    const float* __restrict__ obias)
{
    extern __shared__ char smem[];
    uint32_t sb = smem_u32(smem);
    int tid = threadIdx.x;
    int wid = tid >> 5, lane = tid & 31;

    if (tid < KOFF) ((float*)(smem + OBIAS_OFF))[tid] = __ldg(&obias[tid]);

    int b  = blockIdx.x >> 8;
    int oy = blockIdx.x & 255;
    int ox = tid;

    const float* fb = g_feat + b*CC*HWP;

    float acc[32];                       // [mt2][nt4][4]
    #pragma unroll
    for (int i = 0; i < 32; i++) acc[i] = 0.f;

    uint32_t arow0 = (uint32_t)(wid*32 + (lane & 15)) * 128;
    uint32_t arow1 = arow0 + 16*128;
    uint32_t acol  = (uint32_t)((lane >> 4) * 16);

    #pragma unroll 1
    for (int k = 0; k < 9; k++) {
        __syncthreads();

        int i = k / 3, j = k % 3;
        int iy = oy + i - 1, ix = ox + j - 1;
        bool ok = (iy >= 0 && iy < HH && ix >= 0 && ix < WW);
        int pix_s = ok ? (iy*WW + ix) : 0;

        #pragma unroll 2
        for (int g = 0; g < 16; g++) {
            int ic = g*4;
            float s0 = ok ? __ldg(fb + (ic+0)*HWP + pix_s) : 0.f;
            float s1 = ok ? __ldg(fb + (ic+1)*HWP + pix_s) : 0.f;
            float s2 = ok ? __ldg(fb + (ic+2)*HWP + pix_s) : 0.f;
            float s3 = ok ? __ldg(fb + (ic+3)*HWP + pix_s) : 0.f;
            __nv_bfloat16 h0 = __float2bfloat16_rn(s0);
            __nv_bfloat16 h1 = __float2bfloat16_rn(s1);
            __nv_bfloat16 h2 = __float2bfloat16_rn(s2);
            __nv_bfloat16 h3 = __float2bfloat16_rn(s3);
            __nv_bfloat16 q0 = __float2bfloat16_rn(s0 - __bfloat162float(h0));
            __nv_bfloat16 q1 = __float2bfloat16_rn(s1 - __bfloat162float(h1));
            __nv_bfloat16 q2 = __float2bfloat16_rn(s2 - __bfloat162float(h2));
            __nv_bfloat16 q3 = __float2bfloat16_rn(s3 - __bfloat162float(h3));
            __nv_bfloat162 hA = __halves2bfloat162(h0, h1);
            __nv_bfloat162 hB = __halves2bfloat162(h2, h3);
            __nv_bfloat162 lA = __halves2bfloat162(q0, q1);
            __nv_bfloat162 lB = __halves2bfloat162(q2, q3);
            uint32_t sw = SWZ((uint32_t)(ox*128 + ic*2));
            *(uint2*)(smem + OS_HI + sw) = make_uint2(*(uint32_t*)&hA, *(uint32_t*)&hB);
            *(uint2*)(smem + OS_LO + sw) = make_uint2(*(uint32_t*)&lA, *(uint32_t*)&lB);
        }

        __syncthreads();

        #pragma unroll
        for (int ks = 0; ks < 4; ks++) {
            uint32_t kb = (uint32_t)(ks*32);
            uint32_t aH0[4], aH1[4], aL0[4], aL1[4];
            ldsm4(aH0, sb + OS_HI + SWZ(arow0 + kb + acol));
            ldsm4(aH1, sb + OS_HI + SWZ(arow1 + kb + acol));
            ldsm4(aL0, sb + OS_LO + SWZ(arow0 + kb + acol));
            ldsm4(aL1, sb + OS_LO + SWZ(arow1 + kb + acol));
            #pragma unroll
            for (int ntp = 0; ntp < 2; ntp++) {
                int fidx = (((k*4 + ks)*2 + ntp)*32 + lane)*4;
                uint4 bhv = *(const uint4*)&g_ofragH[fidx];
                uint4 blv = *(const uint4*)&g_ofragL[fidx];
                uint32_t bh[4] = {bhv.x, bhv.y, bhv.z, bhv.w};
                uint32_t bl[4] = {blv.x, blv.y, blv.z, blv.w};
                float* c00 = acc + (0*4 + 2*ntp    )*4;
                float* c10 = acc + (1*4 + 2*ntp    )*4;
                float* c01 = acc + (0*4 + 2*ntp + 1)*4;
                float* c11 = acc + (1*4 + 2*ntp + 1)*4;
                mma16816(c00, aH0, bh);     mma16816(c10, aH1, bh);
                mma16816(c01, aH0, bh + 2); mma16816(c11, aH1, bh + 2);
                mma16816(c00, aL0, bh);     mma16816(c10, aL1, bh);
                mma16816(c01, aL0, bh + 2); mma16816(c11, aL1, bh + 2);
                mma16816(c00, aH0, bl);     mma16816(c10, aH1, bl);
                mma16816(c01, aH0, bl + 2); mma16816(c11, aH1, bl + 2);
            }
        }
    }

    // epilogue: frags -> smem [n][px] (260 pad) -> coalesced g_off stores
    __syncthreads();
    float* ds = (float*)smem;            // 32 x 260 floats = 33280 B
    {
        int mrow = wid*32 + (lane >> 2);
        int ncol = 2*(lane & 3);
        #pragma unroll
        for (int mt = 0; mt < 2; mt++) {
            int m = mrow + mt*16;
            #pragma unroll
            for (int nt = 0; nt < 4; nt++) {
                int n = nt*8 + ncol;
                const float* c = acc + (mt*4 + nt)*4;
                ds[ n   *260 + m    ] = c[0];
                ds[(n+1)*260 + m    ] = c[1];
                ds[ n   *260 + m + 8] = c[2];
                ds[(n+1)*260 + m + 8] = c[3];
            }
        }
    }
    __syncthreads();
    {
        const float* bs = (const float*)(smem + OBIAS_OFF);
        int row_base = oy*WW;
        float* go = g_off + b*KOFF*HWP;
        #pragma unroll
        for (int o = 0; o < KOFF; o++)
            go[o*HWP + row_base + tid] = ds[o*260 + tid] + bs[o];
    }
}

// ---------------------------------------------------------------------------
// Kernel 3: deformable conv — HMMA (round-7 proven: 331us)
// ---------------------------------------------------------------------------
#define S_HI_OFF 0
#define S_LO_OFF 32768
#define BIAS_OFF 66560
#define SMEM3_TOT (66560 + 256)

struct Samp { float w00, w01, w10, w11; int i00, i01, i10, i11; };

__device__ __forceinline__ Samp make_samp(float sy, float sx)
{
    float y0f = floorf(sy), x0f = floorf(sx);
    float dy = sy - y0f,    dx = sx - x0f;

    bool vy0 = (y0f       >= 0.f) && (y0f       <= (float)(HH-1));
    bool vy1 = (y0f + 1.f >= 0.f) && (y0f + 1.f <= (float)(HH-1));
    bool vx0 = (x0f       >= 0.f) && (x0f       <= (float)(WW-1));
    bool vx1 = (x0f + 1.f >= 0.f) && (x0f + 1.f <= (float)(WW-1));

    int y0 = (int)fminf(fmaxf(y0f,       0.f), (float)(HH-1));
    int y1 = (int)fminf(fmaxf(y0f + 1.f, 0.f), (float)(HH-1));
    int x0 = (int)fminf(fmaxf(x0f,       0.f), (float)(WW-1));
    int x1 = (int)fminf(fmaxf(x0f + 1.f, 0.f), (float)(WW-1));

    Samp s;
    s.w00 = (1.f-dy)*(1.f-dx) * ((vy0 && vx0) ? 1.f : 0.f);
    s.w01 = (1.f-dy)*dx       * ((vy0 && vx1) ? 1.f : 0.f);
    s.w10 = dy*(1.f-dx)       * ((vy1 && vx0) ? 1.f : 0.f);
    s.w11 = dy*dx             * ((vy1 && vx1) ? 1.f : 0.f);
    s.i00 = y0*WW + x0;  s.i01 = y0*WW + x1;
    s.i10 = y1*WW + x0;  s.i11 = y1*WW + x1;
    return s;
}

__global__ __launch_bounds__(256, 2) void deform_mma_kernel(
    const float* __restrict__ dbias, float* __restrict__ out)
{
    extern __shared__ char smem[];
    uint32_t sb = smem_u32(smem);
    int tid = threadIdx.x;
    int wid = tid >> 5, lane = tid & 31;

    if (tid < 64) ((float*)(smem + BIAS_OFF))[tid] = __ldg(&dbias[tid]);

    int b  = blockIdx.x >> 8;
    int oy = blockIdx.x & 255;
    int ox = tid;
    int pix = oy*WW + ox;

    const float* fb = g_feat + b*CC*HWP;
    const float* ob = g_off  + b*KOFF*HWP;

    float acc[64];
    #pragma unroll
    for (int i = 0; i < 64; i++) acc[i] = 0.f;

    uint32_t arow0 = (uint32_t)(wid*32 + (lane & 15)) * 128;
    uint32_t arow1 = arow0 + 16*128;
    uint32_t acol  = (uint32_t)((lane >> 4) * 16);

    #pragma unroll 1
    for (int k = 0; k < 9; k++) {
        __syncthreads();

        int i = k / 3, j = k % 3;
        float offy = __ldg(ob + (2*k    )*HWP + pix);
        float offx = __ldg(ob + (2*k + 1)*HWP + pix);
        Samp S = make_samp((float)(oy - 1 + i) + offy,
                           (float)(ox - 1 + j) + offx);

        #pragma unroll 2
        for (int g = 0; g < 16; g++) {
            int ic = g*4;
            float s[4];
            #pragma unroll
            for (int t = 0; t < 4; t++) {
                const float* p = fb + (ic + t)*HWP;
                s[t] = S.w00*__ldg(p + S.i00) + S.w01*__ldg(p + S.i01)
                     + S.w10*__ldg(p + S.i10) + S.w11*__ldg(p + S.i11);
            }
            __nv_bfloat16 h0 = __float2bfloat16_rn(s[0]);
            __nv_bfloat16 h1 = __float2bfloat16_rn(s[1]);
            __nv_bfloat16 h2 = __float2bfloat16_rn(s[2]);
            __nv_bfloat16 h3 = __float2bfloat16_rn(s[3]);
            __nv_bfloat16 q0 = __float2bfloat16_rn(s[0] - __bfloat162float(h0));
            __nv_bfloat16 q1 = __float2bfloat16_rn(s[1] - __bfloat162float(h1));
            __nv_bfloat16 q2 = __float2bfloat16_rn(s[2] - __bfloat162float(h2));
            __nv_bfloat16 q3 = __float2bfloat16_rn(s[3] - __bfloat162float(h3));
            __nv_bfloat162 hA = __halves2bfloat162(h0, h1);
            __nv_bfloat162 hB = __halves2bfloat162(h2, h3);
            __nv_bfloat162 lA = __halves2bfloat162(q0, q1);
            __nv_bfloat162 lB = __halves2bfloat162(q2, q3);
            uint32_t sw = SWZ((uint32_t)(ox*128 + ic*2));
            *(uint2*)(smem + S_HI_OFF + sw) =
                make_uint2(*(uint32_t*)&hA, *(uint32_t*)&hB);
            *(uint2*)(smem + S_LO_OFF + sw) =
                make_uint2(*(uint32_t*)&lA, *(uint32_t*)&lB);
        }

        __syncthreads();

        #pragma unroll
        for (int ks = 0; ks < 4; ks++) {
            uint32_t kb = (uint32_t)(ks*32);
            uint32_t aH0[4], aH1[4], aL0[4], aL1[4];
            ldsm4(aH0, sb + S_HI_OFF + SWZ(arow0 + kb + acol));
            ldsm4(aH1, sb + S_HI_OFF + SWZ(arow1 + kb + acol));
            ldsm4(aL0, sb + S_LO_OFF + SWZ(arow0 + kb + acol));
            ldsm4(aL1, sb + S_LO_OFF + SWZ(arow1 + kb + acol));
            #pragma unroll
            for (int ntp = 0; ntp < 4; ntp++) {
                int fidx = (((k*4 + ks)*4 + ntp)*32 + lane)*4;
                uint4 bhv = *(const uint4*)&g_wfragH[fidx];
                uint4 blv = *(const uint4*)&g_wfragL[fidx];
                uint32_t bh[4] = {bhv.x, bhv.y, bhv.z, bhv.w};
                uint32_t bl[4] = {blv.x, blv.y, blv.z, blv.w};
                float* c00 = acc + (0*8 + 2*ntp    )*4;
                float* c10 = acc + (1*8 + 2*ntp    )*4;
                float* c01 = acc + (0*8 + 2*ntp + 1)*4;
                float* c11 = acc + (1*8 + 2*ntp + 1)*4;
                mma16816(c00, aH0, bh);     mma16816(c10, aH1, bh);
                mma16816(c01, aH0, bh + 2); mma16816(c11, aH1, bh + 2);
                mma16816(c00, aL0, bh);     mma16816(c10, aL1, bh);
                mma16816(c01, aL0, bh + 2); mma16816(c11, aL1, bh + 2);
                mma16816(c00, aH0, bl);     mma16816(c10, aH1, bl);
                mma16816(c01, aH0, bl + 2); mma16816(c11, aH1, bl + 2);
            }
        }
    }

    __syncthreads();
    float* ds = (float*)smem;
    {
        int mrow = wid*32 + (lane >> 2);
        int ncol = 2*(lane & 3);
        #pragma unroll
        for (int mt = 0; mt < 2; mt++) {
            int m = mrow + mt*16;
            #pragma unroll
            for (int nt = 0; nt < 8; nt++) {
                int n = nt*8 + ncol;
                const float* c = acc + (mt*8 + nt)*4;
                ds[ n   *260 + m    ] = c[0];
                ds[(n+1)*260 + m    ] = c[1];
                ds[ n   *260 + m + 8] = c[2];
                ds[(n+1)*260 + m + 8] = c[3];
            }
        }
    }
    __syncthreads();
    {
        const float* bs = (const float*)(smem + BIAS_OFF);
        int row_base = oy*WW;
        #pragma unroll
        for (int t = 0; t < 8; t++) {
            int oc = wid*8 + t;
            float bv = bs[oc];
            #pragma unroll
            for (int h = 0; h < 2; h++) {
                int p4 = h*128 + lane*4;
                float4 v = *(const float4*)&ds[oc*260 + p4];
                v.x += bv; v.y += bv; v.z += bv; v.w += bv;
                *(float4*)&out[(b*CC + oc)*HWP + row_base + p4] = v;
            }
        }
    }
}

// ---------------------------------------------------------------------------
extern "C" void kernel_launch(void* const* d_in, const int* in_sizes, int n_in,
                              void* d_out, int out_size)
{
    const float* x      = (const float*)d_in[0];
    const float* conv_w = (const float*)d_in[1];
    const float* conv_b = (const float*)d_in[2];
    const float* off_w  = (const float*)d_in[3];
    const float* off_b  = (const float*)d_in[4];
    const float* dw     = (const float*)d_in[5];
    const float* db     = (const float*)d_in[6];
    float* out = (float*)d_out;

    const int blocks = BB*HH*WW / 256;   // 1024

    wfrag_kernel  <<<72, 256>>>(dw);
    ofrag_kernel  <<<36, 256>>>(off_w);
    conv1_kernel  <<<blocks, 256>>>(x, conv_w, conv_b);

    cudaFuncSetAttribute(offconv_mma_kernel,
                         cudaFuncAttributeMaxDynamicSharedMemorySize, OSMEM_TOT);
    offconv_mma_kernel<<<BB*HH, 256, OSMEM_TOT>>>(off_b);

    cudaFuncSetAttribute(deform_mma_kernel,
                         cudaFuncAttributeMaxDynamicSharedMemorySize, SMEM3_TOT);
    deform_mma_kernel<<<BB*HH, 256, SMEM3_TOT>>>(db, out);
}